// round 1
// baseline (speedup 1.0000x reference)
#include <cuda_runtime.h>
#include <cstdint>

// Problem constants (B=1)
#define L 768
#define C_IN 384
#define D 32          // C_OUTER
#define E 128         // C_OUT
#define EPS 1e-5f

// ---------------- scratch (no allocations allowed) ----------------
__device__ float g_left[L * D];
__device__ float g_right[L * D];
__device__ float g_rw2[(size_t)L * D * E];   // 12.6 MB
__device__ float g_lin[L * E];

// packed fp32x2 FMA (sm_100+): d = a*b + c per half
__device__ __forceinline__ float2 ffma2(float2 a, float2 b, float2 c) {
    unsigned long long au, bu, cu, r;
    au = *reinterpret_cast<unsigned long long*>(&a);
    bu = *reinterpret_cast<unsigned long long*>(&b);
    cu = *reinterpret_cast<unsigned long long*>(&c);
    asm("fma.rn.f32x2 %0, %1, %2, %3;" : "=l"(r) : "l"(au), "l"(bu), "l"(cu));
    return *reinterpret_cast<float2*>(&r);
}

// ---------------- Kernel A: LayerNorm + left/right projections ----------------
// grid = L, block = 128
__global__ void __launch_bounds__(128) ln_proj_kernel(
    const float* __restrict__ act, const float* __restrict__ mask,
    const float* __restrict__ nw, const float* __restrict__ nb,
    const float* __restrict__ wl, const float* __restrict__ bl,
    const float* __restrict__ wr, const float* __restrict__ br)
{
    __shared__ float s_norm[C_IN];
    __shared__ float red[128];

    const int l = blockIdx.x;
    const int tid = threadIdx.x;
    const float* arow = act + (size_t)l * C_IN;

    float a0 = arow[tid];
    float a1 = arow[tid + 128];
    float a2 = arow[tid + 256];

    // mean
    red[tid] = a0 + a1 + a2;
    __syncthreads();
    for (int ofs = 64; ofs > 0; ofs >>= 1) {
        if (tid < ofs) red[tid] += red[tid + ofs];
        __syncthreads();
    }
    const float mu = red[0] * (1.0f / C_IN);
    __syncthreads();

    // variance
    float d0 = a0 - mu, d1 = a1 - mu, d2 = a2 - mu;
    red[tid] = d0 * d0 + d1 * d1 + d2 * d2;
    __syncthreads();
    for (int ofs = 64; ofs > 0; ofs >>= 1) {
        if (tid < ofs) red[tid] += red[tid + ofs];
        __syncthreads();
    }
    const float rstd = rsqrtf(red[0] * (1.0f / C_IN) + EPS);
    __syncthreads();

    s_norm[tid]       = d0 * rstd * nw[tid]       + nb[tid];
    s_norm[tid + 128] = d1 * rstd * nw[tid + 128] + nb[tid + 128];
    s_norm[tid + 256] = d2 * rstd * nw[tid + 256] + nb[tid + 256];
    __syncthreads();

    // 64 dot products of length 384, 2 threads each (split over c-halves)
    const int o    = tid & 63;          // output index: 0..31 left, 32..63 right
    const int half = tid >> 6;          // 0/1
    const int col  = o & 31;
    const float* w = (o < 32) ? wl : wr;
    float dot = 0.0f;
    const int c0 = half * (C_IN / 2);
    #pragma unroll 8
    for (int c = c0; c < c0 + C_IN / 2; ++c)
        dot += s_norm[c] * w[c * D + col];
    red[tid] = dot;
    __syncthreads();
    if (tid < 64) {
        float v = red[tid] + red[tid + 64];
        const float m = mask[l];
        if (o < 32) g_left [l * D + col] = m * (v + bl[col]);
        else        g_right[l * D + col] = m * (v + br[col]);
    }
}

// ---------------- Kernel B: rw2 / lin precompute ----------------
// grid = L (i), block = E
__global__ void __launch_bounds__(E) prep_kernel(
    const float* __restrict__ wo, const float* __restrict__ bo)
{
    __shared__ float r_s[D];
    const int i = blockIdx.x;
    const int e = threadIdx.x;
    if (e < D) r_s[e] = g_right[i * D + e];
    __syncthreads();

    float acc = 0.0f;
    float* rw2_i = g_rw2 + (size_t)i * D * E;
    #pragma unroll 8
    for (int d = 0; d < D; ++d) {
        const float w1 = wo[d * E + e];          // wo1[d,e]
        const float w2 = wo[(D + d) * E + e];    // wo2[d,e]
        const float rd = r_s[d];
        rw2_i[d * E + e] = fmaf(rd, w1, w2);
        acc = fmaf(rd, w2, acc);
    }
    g_lin[i * E + e] = bo[e] - acc;
}

// ---------------- Kernel C: main GEMM + epilogue ----------------
// grid = (L/128 j-tiles, L i), block = 256
// out[i,j,e] = sum_d left[j,d]*rw2[i,d,e] + lin[i,e]
__global__ void __launch_bounds__(256) pair_kernel(float* __restrict__ out)
{
    __shared__ __align__(16) float rw2_s[D * E];        // [d][e] 16 KB
    __shared__ __align__(16) float left_s[128 * 33];    // padded stride-33
    __shared__ __align__(16) float lin_s[E];

    const int i  = blockIdx.y;
    const int j0 = blockIdx.x * 128;
    const int tid = threadIdx.x;

    // cooperative loads (fully coalesced global reads)
    const float* rw2_i = g_rw2 + (size_t)i * D * E;
    const float* left_g = g_left + (size_t)j0 * D;
    for (int k = tid; k < D * E; k += 256) {
        rw2_s[k] = rw2_i[k];
        const int jj = k >> 5, dd = k & 31;
        left_s[jj * 33 + dd] = left_g[k];
    }
    if (tid < E) lin_s[tid] = g_lin[i * E + tid];
    __syncthreads();

    const int te = tid & 15;        // 16 e-groups of 8 contiguous e
    const int tj = tid >> 4;        // 16 j-groups of 8 contiguous j
    const int e0 = te * 8;
    const float* lbase = &left_s[(tj * 8) * 33];

    float2 acc[8][4];
    #pragma unroll
    for (int r = 0; r < 8; ++r)
        #pragma unroll
        for (int q = 0; q < 4; ++q)
            acc[r][q] = make_float2(0.f, 0.f);

    #pragma unroll 8
    for (int d = 0; d < D; ++d) {
        const float2 b0 = *reinterpret_cast<const float2*>(&rw2_s[d * E + e0 + 0]);
        const float2 b1 = *reinterpret_cast<const float2*>(&rw2_s[d * E + e0 + 2]);
        const float2 b2 = *reinterpret_cast<const float2*>(&rw2_s[d * E + e0 + 4]);
        const float2 b3 = *reinterpret_cast<const float2*>(&rw2_s[d * E + e0 + 6]);
        #pragma unroll
        for (int r = 0; r < 8; ++r) {
            const float av = lbase[r * 33 + d];
            const float2 a2 = make_float2(av, av);
            acc[r][0] = ffma2(a2, b0, acc[r][0]);
            acc[r][1] = ffma2(a2, b1, acc[r][1]);
            acc[r][2] = ffma2(a2, b2, acc[r][2]);
            acc[r][3] = ffma2(a2, b3, acc[r][3]);
        }
    }

    const float2 l0 = *reinterpret_cast<const float2*>(&lin_s[e0 + 0]);
    const float2 l1 = *reinterpret_cast<const float2*>(&lin_s[e0 + 2]);
    const float2 l2 = *reinterpret_cast<const float2*>(&lin_s[e0 + 4]);
    const float2 l3 = *reinterpret_cast<const float2*>(&lin_s[e0 + 6]);

    #pragma unroll
    for (int r = 0; r < 8; ++r) {
        const int j = j0 + tj * 8 + r;
        float* po = out + ((size_t)i * L + j) * E + e0;
        float4 v0, v1;
        v0.x = acc[r][0].x + l0.x;  v0.y = acc[r][0].y + l0.y;
        v0.z = acc[r][1].x + l1.x;  v0.w = acc[r][1].y + l1.y;
        v1.x = acc[r][2].x + l2.x;  v1.y = acc[r][2].y + l2.y;
        v1.z = acc[r][3].x + l3.x;  v1.w = acc[r][3].y + l3.y;
        *reinterpret_cast<float4*>(po)     = v0;
        *reinterpret_cast<float4*>(po + 4) = v1;
    }
}

// ---------------- launch ----------------
extern "C" void kernel_launch(void* const* d_in, const int* in_sizes, int n_in,
                              void* d_out, int out_size)
{
    const float* act  = (const float*)d_in[0];
    const float* mask = (const float*)d_in[1];
    const float* nw   = (const float*)d_in[2];
    const float* nb   = (const float*)d_in[3];
    const float* wl   = (const float*)d_in[4];
    const float* bl   = (const float*)d_in[5];
    const float* wr   = (const float*)d_in[6];
    const float* br   = (const float*)d_in[7];
    const float* wo   = (const float*)d_in[8];
    const float* bo   = (const float*)d_in[9];
    float* out = (float*)d_out;

    ln_proj_kernel<<<L, 128>>>(act, mask, nw, nb, wl, bl, wr, br);
    prep_kernel<<<L, E>>>(wo, bo);
    pair_kernel<<<dim3(L / 128, L), 256>>>(out);
}

// round 2
// speedup vs baseline: 1.8533x; 1.8533x over previous
#include <cuda_runtime.h>
#include <cstdint>

// Problem constants (B=1)
#define L 768
#define C_IN 384
#define D 32          // C_OUTER
#define E 128         // C_OUT
#define EPS 1e-5f

// ---------------- scratch (no allocations allowed) ----------------
__device__ float g_left[L * D];
__device__ float g_right[L * D];
__device__ float g_rw2[(size_t)L * D * E];   // 12.6 MB
__device__ float g_lin[L * E];

// packed fp32x2 FMA (sm_100+): d = a*b + c per half
__device__ __forceinline__ float2 ffma2(float2 a, float2 b, float2 c) {
    unsigned long long au, bu, cu, r;
    au = *reinterpret_cast<unsigned long long*>(&a);
    bu = *reinterpret_cast<unsigned long long*>(&b);
    cu = *reinterpret_cast<unsigned long long*>(&c);
    asm("fma.rn.f32x2 %0, %1, %2, %3;" : "=l"(r) : "l"(au), "l"(bu), "l"(cu));
    return *reinterpret_cast<float2*>(&r);
}

// ---------------- Kernel A: LayerNorm + left/right projections ----------------
// grid = L, block = 256 (one row per block)
__global__ void __launch_bounds__(256) ln_proj_kernel(
    const float* __restrict__ act, const float* __restrict__ mask,
    const float* __restrict__ nw, const float* __restrict__ nb,
    const float* __restrict__ wl, const float* __restrict__ bl,
    const float* __restrict__ wr, const float* __restrict__ br)
{
    __shared__ float s_norm[C_IN];
    __shared__ float warp_sum[8];
    __shared__ float bcast;
    __shared__ float red[256];

    const int l = blockIdx.x;
    const int tid = threadIdx.x;
    const int lane = tid & 31;
    const int wid = tid >> 5;
    const float* arow = act + (size_t)l * C_IN;

    const float x0 = arow[tid];
    const float x1 = (tid < C_IN - 256) ? arow[256 + tid] : 0.0f;

    // ---- mean ----
    float s = x0 + x1;
    #pragma unroll
    for (int o = 16; o > 0; o >>= 1) s += __shfl_xor_sync(0xffffffffu, s, o);
    if (lane == 0) warp_sum[wid] = s;
    __syncthreads();
    if (tid == 0) {
        float t = 0.f;
        #pragma unroll
        for (int w = 0; w < 8; ++w) t += warp_sum[w];
        bcast = t * (1.0f / C_IN);
    }
    __syncthreads();
    const float mu = bcast;

    // ---- variance ----
    const float d0 = x0 - mu;
    const float d1 = (tid < C_IN - 256) ? (x1 - mu) : 0.0f;
    float v = d0 * d0 + d1 * d1;
    #pragma unroll
    for (int o = 16; o > 0; o >>= 1) v += __shfl_xor_sync(0xffffffffu, v, o);
    if (lane == 0) warp_sum[wid] = v;
    __syncthreads();
    if (tid == 0) {
        float t = 0.f;
        #pragma unroll
        for (int w = 0; w < 8; ++w) t += warp_sum[w];
        bcast = rsqrtf(t * (1.0f / C_IN) + EPS);
    }
    __syncthreads();
    const float rstd = bcast;

    s_norm[tid] = d0 * rstd * nw[tid] + nb[tid];
    if (tid < C_IN - 256)
        s_norm[256 + tid] = d1 * rstd * nw[256 + tid] + nb[256 + tid];
    __syncthreads();

    // ---- projections: 64 dots of length 384, 4 threads per dot ----
    const int oc  = tid & 63;          // 0..31 -> left, 32..63 -> right
    const int q   = tid >> 6;          // quarter of the c-range
    const int col = oc & 31;
    const float* w = (oc < 32) ? wl : wr;
    float dot = 0.0f;
    const int c0 = q * (C_IN / 4);
    #pragma unroll 8
    for (int c = c0; c < c0 + C_IN / 4; ++c)
        dot += s_norm[c] * w[c * D + col];
    red[tid] = dot;
    __syncthreads();
    if (tid < 128) red[tid] += red[tid + 128];
    __syncthreads();
    if (tid < 64) {
        const float vv = red[tid] + red[tid + 64];
        const float m = mask[l];
        if (oc < 32) g_left [l * D + col] = m * (vv + bl[col]);
        else         g_right[l * D + col] = m * (vv + br[col]);
    }
}

// ---------------- Kernel B: rw2 / lin precompute ----------------
// grid = L (i), block = E
__global__ void __launch_bounds__(E) prep_kernel(
    const float* __restrict__ wo, const float* __restrict__ bo)
{
    __shared__ float r_s[D];
    const int i = blockIdx.x;
    const int e = threadIdx.x;
    if (e < D) r_s[e] = g_right[i * D + e];
    __syncthreads();

    float acc = 0.0f;
    float* rw2_i = g_rw2 + (size_t)i * D * E;
    #pragma unroll 8
    for (int d = 0; d < D; ++d) {
        const float w1 = wo[d * E + e];          // wo1[d,e]
        const float w2 = wo[(D + d) * E + e];    // wo2[d,e]
        const float rd = r_s[d];
        rw2_i[d * E + e] = fmaf(rd, w1, w2);
        acc = fmaf(rd, w2, acc);
    }
    g_lin[i * E + e] = bo[e] - acc;
}

// ---------------- Kernel C: main GEMM + epilogue ----------------
// grid = (L/128 j-tiles, L i), block = 256
// out[i,j,e] = sum_d left[j,d]*rw2[i,d,e] + lin[i,e]
#define LS 132   // left_s row stride (floats), 8B-aligned, 4-way write conflict only
__global__ void __launch_bounds__(256) pair_kernel(float* __restrict__ out)
{
    __shared__ __align__(16) float rw2_s[D * E];        // [d][e], 16 KB
    __shared__ __align__(16) float left_s[D * LS];      // [d][j] transposed, padded
    __shared__ __align__(16) float lin_s[E];

    const int i   = blockIdx.y;
    const int j0  = blockIdx.x * 128;
    const int tid = threadIdx.x;

    // cooperative loads (float4 global reads)
    const float4* rw2_i4  = reinterpret_cast<const float4*>(g_rw2 + (size_t)i * D * E);
    const float4* left_g4 = reinterpret_cast<const float4*>(g_left + (size_t)j0 * D);
    float4* rw2_s4w = reinterpret_cast<float4*>(rw2_s);
    #pragma unroll
    for (int k4 = tid; k4 < (D * E) / 4; k4 += 256) {
        rw2_s4w[k4] = rw2_i4[k4];
        const float4 v = left_g4[k4];            // j = k4>>3, d0 = (4*k4)&31
        const int jj = k4 >> 3;
        const int dd = (k4 * 4) & 31;
        left_s[(dd + 0) * LS + jj] = v.x;
        left_s[(dd + 1) * LS + jj] = v.y;
        left_s[(dd + 2) * LS + jj] = v.z;
        left_s[(dd + 3) * LS + jj] = v.w;
    }
    if (tid < E) lin_s[tid] = g_lin[i * E + tid];
    __syncthreads();

    const int te = tid & 15;        // e tile: lo = te*4, hi = te*4 + 64
    const int tj = tid >> 4;        // j tile: 8 consecutive rows
    const float4* rw4 = reinterpret_cast<const float4*>(rw2_s);
    const float* lrow0 = &left_s[tj * 8];

    float2 acc[8][4];
    #pragma unroll
    for (int r = 0; r < 8; ++r)
        #pragma unroll
        for (int qq = 0; qq < 4; ++qq)
            acc[r][qq] = make_float2(0.f, 0.f);

    #pragma unroll 4
    for (int d = 0; d < D; ++d) {
        const float4 blv = rw4[d * 32 + te];        // e: te*4 .. te*4+3
        const float4 bhv = rw4[d * 32 + 16 + te];   // e: 64+te*4 ..
        const float* lrow = lrow0 + d * LS;
        const float2 a01 = *reinterpret_cast<const float2*>(lrow + 0);
        const float2 a23 = *reinterpret_cast<const float2*>(lrow + 2);
        const float2 a45 = *reinterpret_cast<const float2*>(lrow + 4);
        const float2 a67 = *reinterpret_cast<const float2*>(lrow + 6);
        const float2 bl0 = make_float2(blv.x, blv.y);
        const float2 bl1 = make_float2(blv.z, blv.w);
        const float2 bh0 = make_float2(bhv.x, bhv.y);
        const float2 bh1 = make_float2(bhv.z, bhv.w);
        const float av[8] = {a01.x, a01.y, a23.x, a23.y, a45.x, a45.y, a67.x, a67.y};
        #pragma unroll
        for (int r = 0; r < 8; ++r) {
            const float2 a2 = make_float2(av[r], av[r]);
            acc[r][0] = ffma2(a2, bl0, acc[r][0]);
            acc[r][1] = ffma2(a2, bl1, acc[r][1]);
            acc[r][2] = ffma2(a2, bh0, acc[r][2]);
            acc[r][3] = ffma2(a2, bh1, acc[r][3]);
        }
    }

    const float4 linL = reinterpret_cast<const float4*>(lin_s)[te];
    const float4 linH = reinterpret_cast<const float4*>(lin_s)[16 + te];

    #pragma unroll
    for (int r = 0; r < 8; ++r) {
        const int j = j0 + tj * 8 + r;
        float4* po = reinterpret_cast<float4*>(out + ((size_t)i * L + j) * E);
        float4 v0, v1;
        v0.x = acc[r][0].x + linL.x;  v0.y = acc[r][0].y + linL.y;
        v0.z = acc[r][1].x + linL.z;  v0.w = acc[r][1].y + linL.w;
        v1.x = acc[r][2].x + linH.x;  v1.y = acc[r][2].y + linH.y;
        v1.z = acc[r][3].x + linH.z;  v1.w = acc[r][3].y + linH.w;
        po[te]      = v0;
        po[16 + te] = v1;
    }
}

// ---------------- launch ----------------
extern "C" void kernel_launch(void* const* d_in, const int* in_sizes, int n_in,
                              void* d_out, int out_size)
{
    const float* act  = (const float*)d_in[0];
    const float* mask = (const float*)d_in[1];
    const float* nw   = (const float*)d_in[2];
    const float* nb   = (const float*)d_in[3];
    const float* wl   = (const float*)d_in[4];
    const float* bl   = (const float*)d_in[5];
    const float* wr   = (const float*)d_in[6];
    const float* br   = (const float*)d_in[7];
    const float* wo   = (const float*)d_in[8];
    const float* bo   = (const float*)d_in[9];
    float* out = (float*)d_out;

    ln_proj_kernel<<<L, 256>>>(act, mask, nw, nb, wl, bl, wr, br);
    prep_kernel<<<L, E>>>(wo, bo);
    pair_kernel<<<dim3(L / 128, L), 256>>>(out);
}